// round 1
// baseline (speedup 1.0000x reference)
#include <cuda_runtime.h>
#include <cuda_bf16.h>
#include <math.h>

// Problem constants
#define BATCH 4
#define SQ    2048
#define SK    2048
#define DMODEL 512
#define PDIM  64
#define NHEAD 8
#define HD    64
#define MROWS (BATCH*SK)          // 8192

// ---------------------------------------------------------------------------
// Device scratch (no cudaMalloc allowed)
// ---------------------------------------------------------------------------
__device__ float g_H [(long)MROWS*DMODEL];           // 16.7 MB
__device__ float g_E [(long)MROWS*DMODEL];           // 16.7 MB
__device__ float g_Qp[(long)BATCH*NHEAD*SQ*HD];      // 16.7 MB  (B,H,Sq,64)
__device__ float g_Kp[(long)BATCH*NHEAD*SK*HD];      // 16.7 MB  (B,H,Sk,64)
__device__ float g_expS[(long)BATCH*NHEAD*SQ*SK];    // 536.9 MB (BH,Sq,Sk)
__device__ float g_headSum[(long)BATCH*NHEAD*SQ];    // 256 KB

// ---------------------------------------------------------------------------
// Zero head sums
// ---------------------------------------------------------------------------
__global__ void zero_hs_kernel() {
    int i = blockIdx.x * blockDim.x + threadIdx.x;
    if (i < BATCH*NHEAD*SQ) g_headSum[i] = 0.f;
}

// ---------------------------------------------------------------------------
// Generic tiled fp32 GEMM: C = act(A @ W + bias)
//   BM=BN=64, BK=16, 256 threads, 4x4 micro-tile
//   a_mode:  0 -> A is [M,K] row-major
//            1 -> A is concat(key[512], pos_emb[kwpos][64]); K must be 576
//   act:     0 none, 1 relu, 2 tanh
//   out_mode:0 -> C row-major [M,N]
//            1 -> head-split: M = B*S rows, N = 8*64; write (B,H,S,64)
// ---------------------------------------------------------------------------
__global__ void gemm_tiled(const float* __restrict__ A,
                           const float* __restrict__ W,
                           const float* __restrict__ bias,
                           float* __restrict__ C,
                           int M, int K, int N,
                           long a_bstride, long w_bstride, long c_bstride,
                           int act, int a_mode,
                           const int* __restrict__ kwpos,
                           const float* __restrict__ pos_emb,
                           int out_mode, int S)
{
    const float* Ab = A + (long)blockIdx.z * a_bstride;
    const float* Wb = W + (long)blockIdx.z * w_bstride;
    float*       Cb = C + (long)blockIdx.z * c_bstride;

    int m0 = blockIdx.y * 64;
    int n0 = blockIdx.x * 64;
    int tid = threadIdx.x;
    int tx = tid & 15, ty = tid >> 4;

    __shared__ float As[16][64];   // [k][m]
    __shared__ float Ws[16][64];   // [k][n]

    float acc[4][4] = {};

    int a_r  = tid >> 2;          // 0..63
    int a_c4 = (tid & 3) * 4;     // 0,4,8,12
    int w_r  = tid >> 6;          // 0..3
    int w_c  = tid & 63;

    for (int k0 = 0; k0 < K; k0 += 16) {
        // --- A tile ---
        float4 av;
        {
            int m  = m0 + a_r;
            int kk = k0 + a_c4;
            if (a_mode == 0) {
                av = *(const float4*)&Ab[(long)m * K + kk];
            } else {
                if (kk < 512) {
                    av = *(const float4*)&Ab[(long)m * 512 + kk];
                } else {
                    int p = kwpos[m];
                    av = *(const float4*)&pos_emb[(long)p * PDIM + (kk - 512)];
                }
            }
        }
        As[a_c4+0][a_r] = av.x;
        As[a_c4+1][a_r] = av.y;
        As[a_c4+2][a_r] = av.z;
        As[a_c4+3][a_r] = av.w;
        // --- W tile ---
        #pragma unroll
        for (int i = 0; i < 4; i++)
            Ws[w_r + i*4][w_c] = Wb[(long)(k0 + w_r + i*4) * N + n0 + w_c];
        __syncthreads();

        #pragma unroll
        for (int kk = 0; kk < 16; kk++) {
            float4 a4 = *(const float4*)&As[kk][ty*4];
            float4 b4 = *(const float4*)&Ws[kk][tx*4];
            float a[4] = {a4.x, a4.y, a4.z, a4.w};
            float b[4] = {b4.x, b4.y, b4.z, b4.w};
            #pragma unroll
            for (int i = 0; i < 4; i++)
                #pragma unroll
                for (int j = 0; j < 4; j++)
                    acc[i][j] = fmaf(a[i], b[j], acc[i][j]);
        }
        __syncthreads();
    }

    #pragma unroll
    for (int i = 0; i < 4; i++) {
        int m = m0 + ty*4 + i;
        #pragma unroll
        for (int j = 0; j < 4; j++) {
            int n = n0 + tx*4 + j;
            float v = acc[i][j] + (bias ? bias[n] : 0.f);
            if (act == 1)      v = fmaxf(v, 0.f);
            else if (act == 2) v = tanhf(v);
            if (out_mode == 0) {
                Cb[(long)m * N + n] = v;
            } else {
                int b = m / S, s = m % S;
                int h = n >> 6, d = n & 63;
                Cb[(((long)(b*NHEAD + h) * S + s) << 6) + d] = v;
            }
        }
    }
}

// ---------------------------------------------------------------------------
// Score kernel: per (b,h), 64x64 tile of exp(Q·K^T / 8); accumulate row sums.
//   grid: (Sk/64, Sq/64, B*H), 256 threads
// ---------------------------------------------------------------------------
__global__ void score_kernel()
{
    int bh = blockIdx.z;
    int q0 = blockIdx.y * 64;
    int k0 = blockIdx.x * 64;
    const float* Q  = g_Qp + (long)bh * SQ * HD;
    const float* Kb = g_Kp + (long)bh * SK * HD;

    __shared__ float sQ[64][64];   // [d][q]
    __shared__ float sK[64][64];   // [d][k]

    int tid = threadIdx.x;
    {
        int row = tid >> 4;            // 0..15
        int d0  = (tid & 15) * 4;      // 0..60
        #pragma unroll
        for (int it = 0; it < 4; it++) {
            int rr = row + it*16;
            float4 qv = *(const float4*)&Q [(long)(q0+rr)*HD + d0];
            sQ[d0+0][rr]=qv.x; sQ[d0+1][rr]=qv.y; sQ[d0+2][rr]=qv.z; sQ[d0+3][rr]=qv.w;
            float4 kv = *(const float4*)&Kb[(long)(k0+rr)*HD + d0];
            sK[d0+0][rr]=kv.x; sK[d0+1][rr]=kv.y; sK[d0+2][rr]=kv.z; sK[d0+3][rr]=kv.w;
        }
    }
    __syncthreads();

    int tx = tid & 15, ty = tid >> 4;
    float acc[4][4] = {};
    #pragma unroll
    for (int d = 0; d < 64; d++) {
        float4 a4 = *(const float4*)&sQ[d][ty*4];
        float4 b4 = *(const float4*)&sK[d][tx*4];
        float a[4] = {a4.x, a4.y, a4.z, a4.w};
        float b[4] = {b4.x, b4.y, b4.z, b4.w};
        #pragma unroll
        for (int i = 0; i < 4; i++)
            #pragma unroll
            for (int j = 0; j < 4; j++)
                acc[i][j] = fmaf(a[i], b[j], acc[i][j]);
    }

    __shared__ float sRed[64][17];
    #pragma unroll
    for (int i = 0; i < 4; i++) {
        int q = q0 + ty*4 + i;
        float e0 = __expf(acc[i][0] * 0.125f);
        float e1 = __expf(acc[i][1] * 0.125f);
        float e2 = __expf(acc[i][2] * 0.125f);
        float e3 = __expf(acc[i][3] * 0.125f);
        *(float4*)&g_expS[((long)bh*SQ + q)*SK + k0 + tx*4] =
            make_float4(e0, e1, e2, e3);
        sRed[ty*4 + i][tx] = e0 + e1 + e2 + e3;
    }
    __syncthreads();
    if (tid < 64) {
        float s = 0.f;
        #pragma unroll
        for (int t = 0; t < 16; t++) s += sRed[tid][t];
        atomicAdd(&g_headSum[(long)bh*SQ + q0 + tid], s);
    }
}

// ---------------------------------------------------------------------------
// Combine kernel: one CTA per (b,q) row.
//   attn = mean_h( expS_h / headSum_h ); t = attn * dist_w; adjusted = softmax(t)
//   Second softmax done max-free (t in [0,1]) with full normalization in-block.
// ---------------------------------------------------------------------------
__global__ void combine_kernel(const int* __restrict__ kwpos,
                               float* __restrict__ adj)
{
    int bq = blockIdx.x;           // 0..8191
    int b  = bq >> 11;
    int q  = bq & 2047;
    int tid = threadIdx.x;         // 256

    __shared__ float invHS[NHEAD];
    if (tid < NHEAD)
        invHS[tid] = 1.0f / g_headSum[(long)(b*NHEAD + tid)*SQ + q];
    __syncthreads();

    float e[8];
    float sum = 0.f;
    #pragma unroll
    for (int i = 0; i < 8; i++) {
        int k = tid + i*256;
        float a = 0.f;
        #pragma unroll
        for (int h = 0; h < NHEAD; h++)
            a = fmaf(g_expS[((long)(b*NHEAD + h)*SQ + q)*SK + k], invHS[h], a);
        a *= 0.125f;   // mean over heads
        int kp = kwpos[b*SK + k];
        float dw = 1.0f / (1.0f + fabsf((float)(q - kp)));
        e[i] = __expf(a * dw);
        sum += e[i];
    }

    __shared__ float red[256];
    red[tid] = sum;
    __syncthreads();
    #pragma unroll
    for (int s = 128; s > 0; s >>= 1) {
        if (tid < s) red[tid] += red[tid + s];
        __syncthreads();
    }
    float inv = 1.0f / red[0];

    long base = (long)bq * SK;
    #pragma unroll
    for (int i = 0; i < 8; i++)
        adj[base + tid + i*256] = e[i] * inv;
}

// ---------------------------------------------------------------------------
// Host launcher
// ---------------------------------------------------------------------------
extern "C" void kernel_launch(void* const* d_in, const int* in_sizes, int n_in,
                              void* d_out, int out_size)
{
    const float* query   = (const float*)d_in[0];
    const float* key     = (const float*)d_in[1];
    const float* value   = (const float*)d_in[2];
    const int*   kwpos   = (const int*)  d_in[3];
    const float* pos_emb = (const float*)d_in[4];
    const float* w1      = (const float*)d_in[5];
    const float* b1      = (const float*)d_in[6];
    const float* w2      = (const float*)d_in[7];
    const float* b2      = (const float*)d_in[8];
    const float* wq      = (const float*)d_in[9];
    const float* bq      = (const float*)d_in[10];
    const float* wk      = (const float*)d_in[11];
    const float* bk      = (const float*)d_in[12];

    float* out = (float*)d_out;                          // (B,Sq,D)
    float* adj = out + (long)BATCH*SQ*DMODEL;            // (B,Sq,Sk)

    float *gH, *gE, *gQp, *gKp;
    cudaGetSymbolAddress((void**)&gH,  g_H);
    cudaGetSymbolAddress((void**)&gE,  g_E);
    cudaGetSymbolAddress((void**)&gQp, g_Qp);
    cudaGetSymbolAddress((void**)&gKp, g_Kp);

    // 0) zero head sums
    zero_hs_kernel<<<(BATCH*NHEAD*SQ + 255)/256, 256>>>();

    // 1) H = relu(concat(key, pe) @ w1 + b1)   M=8192,K=576,N=512
    gemm_tiled<<<dim3(DMODEL/64, MROWS/64, 1), 256>>>(
        key, w1, b1, gH, MROWS, 576, DMODEL,
        0, 0, 0, /*act=*/1, /*a_mode=*/1, kwpos, pos_emb, /*out_mode=*/0, SK);

    // 2) E = tanh(H @ w2 + b2)                 M=8192,K=512,N=512
    gemm_tiled<<<dim3(DMODEL/64, MROWS/64, 1), 256>>>(
        gH, w2, b2, gE, MROWS, DMODEL, DMODEL,
        0, 0, 0, /*act=*/2, 0, nullptr, nullptr, 0, SK);

    // 3) Kp = E @ wk + bk  -> (B,H,Sk,64)
    gemm_tiled<<<dim3(DMODEL/64, MROWS/64, 1), 256>>>(
        gE, wk, bk, gKp, MROWS, DMODEL, DMODEL,
        0, 0, 0, 0, 0, nullptr, nullptr, /*out_mode=*/1, SK);

    // 4) Qp = query @ wq + bq -> (B,H,Sq,64)
    gemm_tiled<<<dim3(DMODEL/64, (BATCH*SQ)/64, 1), 256>>>(
        query, wq, bq, gQp, BATCH*SQ, DMODEL, DMODEL,
        0, 0, 0, 0, 0, nullptr, nullptr, /*out_mode=*/1, SQ);

    // 5) expS = exp(Q·K^T / 8), headSum accumulation
    score_kernel<<<dim3(SK/64, SQ/64, BATCH*NHEAD), 256>>>();

    // 6) adjusted = softmax( mean_h(softmax_h) * dist_w )  (fully normalized)
    combine_kernel<<<BATCH*SQ, 256>>>(kwpos, adj);

    // 7) out = adjusted @ value    batched: M=2048,K=2048,N=512, z=B
    gemm_tiled<<<dim3(DMODEL/64, SQ/64, BATCH), 256>>>(
        adj, value, nullptr, out, SQ, SK, DMODEL,
        (long)SQ*SK, (long)SK*DMODEL, (long)SQ*DMODEL,
        0, 0, nullptr, nullptr, 0, SQ);
}

// round 2
// speedup vs baseline: 4.7837x; 4.7837x over previous
#include <cuda_runtime.h>
#include <cuda_bf16.h>
#include <math.h>
#include <stdint.h>

#define BATCH 4
#define SQ    2048
#define SK    2048
#define DMODEL 512
#define NHEAD 8
#define MROWS (BATCH*SK)   // 8192

// ---------------------------------------------------------------------------
// Device scratch (bf16 where possible)
// ---------------------------------------------------------------------------
__device__ __align__(16) __nv_bfloat16 g_KP  [(long)MROWS*576];
__device__ __align__(16) __nv_bfloat16 g_Qb  [(long)MROWS*512];
__device__ __align__(16) __nv_bfloat16 g_w1t [512*576];
__device__ __align__(16) __nv_bfloat16 g_w2t [512*512];
__device__ __align__(16) __nv_bfloat16 g_wqt [512*512];
__device__ __align__(16) __nv_bfloat16 g_wkt [512*512];
__device__ __align__(16) __nv_bfloat16 g_H   [(long)MROWS*512];
__device__ __align__(16) __nv_bfloat16 g_E   [(long)MROWS*512];
__device__ __align__(16) __nv_bfloat16 g_Qp  [(long)MROWS*512];   // (B,H,Sq,64)
__device__ __align__(16) __nv_bfloat16 g_Kp  [(long)MROWS*512];   // (B,H,Sk,64)
__device__ __align__(16) __nv_bfloat16 g_expS[(long)BATCH*NHEAD*SQ*SK]; // 268MB
__device__ __align__(16) __nv_bfloat16 g_delta[(long)BATCH*SQ*SK];      // 33.6MB
__device__ __align__(16) __nv_bfloat16 g_valT[(long)BATCH*512*2048];    // 8.4MB
__device__ float g_sv[BATCH*512];
__device__ float g_headSum[(long)BATCH*NHEAD*SQ];

// ---------------------------------------------------------------------------
__global__ void zero_kernel() {
    int i = blockIdx.x * blockDim.x + threadIdx.x;
    if (i < BATCH*NHEAD*SQ) g_headSum[i] = 0.f;
    if (i < BATCH*512)      g_sv[i] = 0.f;
}

// concat(key, pos_emb[kwpos]) -> bf16 [8192, 576]
__global__ void convert_concat(const float* __restrict__ key,
                               const int* __restrict__ kwpos,
                               const float* __restrict__ pe)
{
    int i = blockIdx.x * blockDim.x + threadIdx.x;   // one 4-elem chunk
    if (i >= MROWS * 144) return;
    int row = i / 144, c4 = (i % 144) * 4;
    float4 v;
    if (c4 < 512) v = *(const float4*)&key[(long)row*512 + c4];
    else { int p = kwpos[row]; v = *(const float4*)&pe[(long)p*64 + (c4-512)]; }
    __nv_bfloat162 p0, p1;
    p0.x = __float2bfloat16(v.x); p0.y = __float2bfloat16(v.y);
    p1.x = __float2bfloat16(v.z); p1.y = __float2bfloat16(v.w);
    __nv_bfloat16* d = &g_KP[(long)row*576 + c4];
    *(__nv_bfloat162*)&d[0] = p0;
    *(__nv_bfloat162*)&d[2] = p1;
}

// fp32 -> bf16 flat copy (n4 = count/4)
__global__ void conv_bf16(const float* __restrict__ src,
                          __nv_bfloat16* __restrict__ dst, int n4)
{
    int i = blockIdx.x * blockDim.x + threadIdx.x;
    if (i >= n4) return;
    float4 v = *(const float4*)&src[(long)i*4];
    __nv_bfloat162 p0, p1;
    p0.x = __float2bfloat16(v.x); p0.y = __float2bfloat16(v.y);
    p1.x = __float2bfloat16(v.z); p1.y = __float2bfloat16(v.w);
    *(__nv_bfloat162*)&dst[(long)i*4]   = p0;
    *(__nv_bfloat162*)&dst[(long)i*4+2] = p1;
}

// transpose + convert: dst[c][r] = bf16(src[r][c]); R,C multiples of 32
__global__ void transpose_conv(const float* __restrict__ src,
                               __nv_bfloat16* __restrict__ dst,
                               int R, int C, long sstr, long dstr)
{
    __shared__ float t[32][33];
    src += (long)blockIdx.z * sstr;
    dst += (long)blockIdx.z * dstr;
    int r0 = blockIdx.y * 32, c0 = blockIdx.x * 32;
    int tx = threadIdx.x & 31, ty = threadIdx.x >> 5;   // 32x8
    #pragma unroll
    for (int i = 0; i < 4; i++)
        t[ty + i*8][tx] = src[(long)(r0 + ty + i*8)*C + c0 + tx];
    __syncthreads();
    #pragma unroll
    for (int i = 0; i < 4; i++)
        dst[(long)(c0 + ty + i*8)*R + r0 + tx] = __float2bfloat16(t[tx][ty + i*8]);
}

// column sums of value per batch: sv[b][d] += sum over k-chunk
__global__ void colsum_kernel(const float* __restrict__ value)
{
    int b = blockIdx.z;
    int d = blockIdx.x * 128 + threadIdx.x;
    int k0 = blockIdx.y * 128;
    float s = 0.f;
    const float* base = value + ((long)b*SK + k0)*512 + d;
    #pragma unroll 8
    for (int k = 0; k < 128; k++) s += base[(long)k*512];
    atomicAdd(&g_sv[b*512 + d], s);
}

// ---------------------------------------------------------------------------
// Unified bf16 tensor-core GEMM: C = epi(A[M,K] @ Bt[N,K]^T + bias)
//   Tiles: 128x128x32, 256 threads (8 warps, 2x4), warp tile 64x32
// EPI: 0 relu->bf16[M,512]   1 tanh->bf16[M,512]   2 bias->bf16 head-split
//      3 exp(x/8)->bf16[M,2048] + rowsum atomics    4 +sv/2048 -> fp32[M,512]
// ---------------------------------------------------------------------------
__device__ __forceinline__ void ldm_x4(uint32_t& r0, uint32_t& r1,
                                       uint32_t& r2, uint32_t& r3, uint32_t a) {
    asm volatile("ldmatrix.sync.aligned.m8n8.x4.shared.b16 {%0,%1,%2,%3}, [%4];"
                 : "=r"(r0), "=r"(r1), "=r"(r2), "=r"(r3) : "r"(a));
}
__device__ __forceinline__ void mma16816(float* c, uint32_t a0, uint32_t a1,
                                         uint32_t a2, uint32_t a3,
                                         uint32_t b0, uint32_t b1) {
    asm volatile("mma.sync.aligned.m16n8k16.row.col.f32.bf16.bf16.f32 "
                 "{%0,%1,%2,%3},{%4,%5,%6,%7},{%8,%9},{%0,%1,%2,%3};"
                 : "+f"(c[0]), "+f"(c[1]), "+f"(c[2]), "+f"(c[3])
                 : "r"(a0), "r"(a1), "r"(a2), "r"(a3), "r"(b0), "r"(b1));
}

template<int EPI>
__global__ void __launch_bounds__(256)
gemm_mma(const __nv_bfloat16* __restrict__ A,
         const __nv_bfloat16* __restrict__ Bt,
         const float* __restrict__ bias,
         __nv_bfloat16* __restrict__ Cb,
         float* __restrict__ Cf,
         int K, long a_bstr, long b_bstr, long c_bstr,
         int S, const float* __restrict__ sv,
         float* __restrict__ rowsum)
{
    __shared__ __align__(16) __nv_bfloat16 sA[2][128][40];
    __shared__ __align__(16) __nv_bfloat16 sB[2][128][40];
    __shared__ float srs[128];

    const int tid = threadIdx.x, lane = tid & 31, wid = tid >> 5;
    const int wm = wid >> 2, wn = wid & 3;
    const int g = lane >> 2, tg = lane & 3;
    const int z = blockIdx.z;
    const int m0 = blockIdx.y * 128, n0 = blockIdx.x * 128;

    A  += (long)z * a_bstr;
    Bt += (long)z * b_bstr;

    if (EPI == 3 && tid < 128) srs[tid] = 0.f;

    float acc[4][4][4];
    #pragma unroll
    for (int i = 0; i < 4; i++)
        #pragma unroll
        for (int j = 0; j < 4; j++)
            #pragma unroll
            for (int r = 0; r < 4; r++) acc[i][j][r] = 0.f;

    const int nk = K >> 5;

    auto prefetch = [&](int t, int buf) {
        int kt = t * 32;
        #pragma unroll
        for (int i = 0; i < 2; i++) {
            int ch = tid + i*256;
            int r = ch >> 2, off = (ch & 3) * 8;
            uint32_t da = (uint32_t)__cvta_generic_to_shared(&sA[buf][r][off]);
            const __nv_bfloat16* ga = A + (long)(m0 + r)*K + kt + off;
            asm volatile("cp.async.cg.shared.global [%0], [%1], 16;" :: "r"(da), "l"(ga));
            uint32_t db = (uint32_t)__cvta_generic_to_shared(&sB[buf][r][off]);
            const __nv_bfloat16* gb = Bt + (long)(n0 + r)*K + kt + off;
            asm volatile("cp.async.cg.shared.global [%0], [%1], 16;" :: "r"(db), "l"(gb));
        }
    };

    prefetch(0, 0);
    asm volatile("cp.async.commit_group;");

    const int arow = (lane & 7) + ((lane & 8) ? 8 : 0);
    const int acol = (lane & 16) ? 8 : 0;
    const int brow = ((lane >> 4) & 1) * 8 + (lane & 7);
    const int bcol = ((lane >> 3) & 1) * 8;

    for (int t = 0; t < nk; ++t) {
        if (t + 1 < nk) {
            prefetch(t + 1, (t + 1) & 1);
            asm volatile("cp.async.commit_group;");
            asm volatile("cp.async.wait_group 1;");
        } else {
            asm volatile("cp.async.wait_group 0;");
        }
        __syncthreads();
        int buf = t & 1;
        #pragma unroll
        for (int ks = 0; ks < 2; ++ks) {
            uint32_t a[4][4], bq_[4][2];
            #pragma unroll
            for (int mi = 0; mi < 4; ++mi) {
                uint32_t ad = (uint32_t)__cvta_generic_to_shared(
                    &sA[buf][wm*64 + mi*16 + arow][ks*16 + acol]);
                ldm_x4(a[mi][0], a[mi][1], a[mi][2], a[mi][3], ad);
            }
            #pragma unroll
            for (int p = 0; p < 2; ++p) {
                uint32_t bd = (uint32_t)__cvta_generic_to_shared(
                    &sB[buf][wn*32 + p*16 + brow][ks*16 + bcol]);
                ldm_x4(bq_[2*p][0], bq_[2*p][1], bq_[2*p+1][0], bq_[2*p+1][1], bd);
            }
            #pragma unroll
            for (int mi = 0; mi < 4; ++mi)
                #pragma unroll
                for (int nj = 0; nj < 4; ++nj)
                    mma16816(acc[mi][nj], a[mi][0], a[mi][1], a[mi][2], a[mi][3],
                             bq_[nj][0], bq_[nj][1]);
        }
        __syncthreads();
    }

    // ------------------------- epilogue -------------------------
    #pragma unroll
    for (int mi = 0; mi < 4; ++mi) {
        #pragma unroll
        for (int half = 0; half < 2; ++half) {
            int m = m0 + wm*64 + mi*16 + g + half*8;
            float rsum = 0.f;
            #pragma unroll
            for (int nj = 0; nj < 4; ++nj) {
                int n = n0 + wn*32 + nj*8 + tg*2;
                float v0 = acc[mi][nj][half*2 + 0];
                float v1 = acc[mi][nj][half*2 + 1];
                if (EPI <= 2) {
                    v0 += bias[n]; v1 += bias[n+1];
                    if (EPI == 0) { v0 = fmaxf(v0, 0.f); v1 = fmaxf(v1, 0.f); }
                    if (EPI == 1) { v0 = tanhf(v0);      v1 = tanhf(v1); }
                    __nv_bfloat162 pk;
                    pk.x = __float2bfloat16(v0); pk.y = __float2bfloat16(v1);
                    if (EPI == 2) {
                        int b = m / S, s = m - b*S;
                        int h = n >> 6, d = n & 63;
                        long idx = (((long)(b*NHEAD + h)*S + s) << 6) + d;
                        *(__nv_bfloat162*)&Cb[idx] = pk;
                    } else {
                        *(__nv_bfloat162*)&Cb[(long)m*512 + n] = pk;
                    }
                } else if (EPI == 3) {
                    v0 = __expf(v0 * 0.125f);
                    v1 = __expf(v1 * 0.125f);
                    __nv_bfloat162 pk;
                    pk.x = __float2bfloat16(v0); pk.y = __float2bfloat16(v1);
                    *(__nv_bfloat162*)&Cb[(long)z*c_bstr + (long)m*2048 + n] = pk;
                    rsum += v0 + v1;
                } else { // EPI == 4
                    const float* svb = sv + (long)z*512;
                    float o0 = v0 + svb[n]   * (1.f/2048.f);
                    float o1 = v1 + svb[n+1] * (1.f/2048.f);
                    *(float2*)&Cf[(long)z*c_bstr + (long)m*512 + n] = make_float2(o0, o1);
                }
            }
            if (EPI == 3) {
                rsum += __shfl_xor_sync(0xffffffffu, rsum, 1);
                rsum += __shfl_xor_sync(0xffffffffu, rsum, 2);
                if (tg == 0) atomicAdd(&srs[m - m0], rsum);
            }
        }
    }
    if (EPI == 3) {
        __syncthreads();
        if (tid < 128) atomicAdd(&rowsum[(long)z*S + m0 + tid], srs[tid]);
    }
}

// ---------------------------------------------------------------------------
// Combine: attn = mean_h(expS_h/Z_h); adjusted = softmax(attn * dist_w)
// Writes fp32 adjusted (output) and bf16 delta = adjusted - 1/2048
// ---------------------------------------------------------------------------
__global__ void combine_kernel(const int* __restrict__ kwpos,
                               float* __restrict__ adj)
{
    int bq = blockIdx.x;
    int b  = bq >> 11;
    int q  = bq & 2047;
    int tid = threadIdx.x;         // 256

    __shared__ float invHS[NHEAD];
    if (tid < NHEAD)
        invHS[tid] = 1.0f / g_headSum[(long)(b*NHEAD + tid)*SQ + q];
    __syncthreads();

    float e[8];
    float sum = 0.f;
    #pragma unroll
    for (int i = 0; i < 8; i++) {
        int k = tid + i*256;
        float a = 0.f;
        #pragma unroll
        for (int h = 0; h < NHEAD; h++)
            a = fmaf(__bfloat162float(
                    g_expS[((long)(b*NHEAD + h)*SQ + q)*SK + k]), invHS[h], a);
        a *= 0.125f;
        int kp = kwpos[b*SK + k];
        float dw = 1.0f / (1.0f + fabsf((float)(q - kp)));
        e[i] = __expf(a * dw);
        sum += e[i];
    }

    // block reduce
    #pragma unroll
    for (int s = 16; s > 0; s >>= 1) sum += __shfl_xor_sync(0xffffffffu, sum, s);
    __shared__ float wred[8];
    if ((tid & 31) == 0) wred[tid >> 5] = sum;
    __syncthreads();
    float tot = wred[0];
    #pragma unroll
    for (int w = 1; w < 8; w++) tot += wred[w];
    float inv = 1.0f / tot;

    long base = (long)bq * SK;
    #pragma unroll
    for (int i = 0; i < 8; i++) {
        int k = tid + i*256;
        float av = e[i] * inv;
        adj[base + k] = av;
        g_delta[base + k] = __float2bfloat16(av - (1.f/2048.f));
    }
}

// ---------------------------------------------------------------------------
extern "C" void kernel_launch(void* const* d_in, const int* in_sizes, int n_in,
                              void* d_out, int out_size)
{
    const float* query   = (const float*)d_in[0];
    const float* key     = (const float*)d_in[1];
    const float* value   = (const float*)d_in[2];
    const int*   kwpos   = (const int*)  d_in[3];
    const float* pos_emb = (const float*)d_in[4];
    const float* w1      = (const float*)d_in[5];
    const float* b1      = (const float*)d_in[6];
    const float* w2      = (const float*)d_in[7];
    const float* b2      = (const float*)d_in[8];
    const float* wq      = (const float*)d_in[9];
    const float* bq      = (const float*)d_in[10];
    const float* wk      = (const float*)d_in[11];
    const float* bk      = (const float*)d_in[12];

    float* out = (float*)d_out;                          // (B,Sq,D)
    float* adj = out + (long)BATCH*SQ*DMODEL;            // (B,Sq,Sk)

    __nv_bfloat16 *gKP, *gQb, *gw1t, *gw2t, *gwqt, *gwkt, *gH, *gE, *gQp, *gKp,
                  *gexpS, *gdelta, *gvalT;
    float *gsv, *ghs;
    cudaGetSymbolAddress((void**)&gKP,   g_KP);
    cudaGetSymbolAddress((void**)&gQb,   g_Qb);
    cudaGetSymbolAddress((void**)&gw1t,  g_w1t);
    cudaGetSymbolAddress((void**)&gw2t,  g_w2t);
    cudaGetSymbolAddress((void**)&gwqt,  g_wqt);
    cudaGetSymbolAddress((void**)&gwkt,  g_wkt);
    cudaGetSymbolAddress((void**)&gH,    g_H);
    cudaGetSymbolAddress((void**)&gE,    g_E);
    cudaGetSymbolAddress((void**)&gQp,   g_Qp);
    cudaGetSymbolAddress((void**)&gKp,   g_Kp);
    cudaGetSymbolAddress((void**)&gexpS, g_expS);
    cudaGetSymbolAddress((void**)&gdelta,g_delta);
    cudaGetSymbolAddress((void**)&gvalT, g_valT);
    cudaGetSymbolAddress((void**)&gsv,   g_sv);
    cudaGetSymbolAddress((void**)&ghs,   g_headSum);

    // prep
    zero_kernel<<<(BATCH*NHEAD*SQ + 255)/256, 256>>>();
    convert_concat<<<(MROWS*144 + 255)/256, 256>>>(key, kwpos, pos_emb);
    conv_bf16<<<(MROWS*512/4 + 255)/256, 256>>>(query, gQb, MROWS*512/4);
    transpose_conv<<<dim3(16, 18, 1), 256>>>(w1, gw1t, 576, 512, 0, 0);
    transpose_conv<<<dim3(16, 16, 1), 256>>>(w2, gw2t, 512, 512, 0, 0);
    transpose_conv<<<dim3(16, 16, 1), 256>>>(wq, gwqt, 512, 512, 0, 0);
    transpose_conv<<<dim3(16, 16, 1), 256>>>(wk, gwkt, 512, 512, 0, 0);
    transpose_conv<<<dim3(16, 64, BATCH), 256>>>(value, gvalT, SK, 512,
                                                 (long)SK*512, (long)512*SK);
    colsum_kernel<<<dim3(4, 16, BATCH), 128>>>(value);

    // 1) H = relu(KP @ w1 + b1)
    gemm_mma<0><<<dim3(4, 64, 1), 256>>>(gKP, gw1t, b1, gH, nullptr,
                                         576, 0, 0, 0, SK, nullptr, nullptr);
    // 2) E = tanh(H @ w2 + b2)
    gemm_mma<1><<<dim3(4, 64, 1), 256>>>(gH, gw2t, b2, gE, nullptr,
                                         512, 0, 0, 0, SK, nullptr, nullptr);
    // 3) Kp = E @ wk + bk   (head-split)
    gemm_mma<2><<<dim3(4, 64, 1), 256>>>(gE, gwkt, bk, gKp, nullptr,
                                         512, 0, 0, 0, SK, nullptr, nullptr);
    // 4) Qp = query @ wq + bq (head-split)
    gemm_mma<2><<<dim3(4, 64, 1), 256>>>(gQb, gwqt, bq, gQp, nullptr,
                                         512, 0, 0, 0, SQ, nullptr, nullptr);
    // 5) expS = exp(Qp·Kp^T / 8) per (b,h); rowsum -> headSum
    gemm_mma<3><<<dim3(16, 16, BATCH*NHEAD), 256>>>(
        gQp, gKp, nullptr, gexpS, nullptr,
        64, (long)SQ*64, (long)SK*64, (long)SQ*SK, SQ, nullptr, ghs);
    // 6) combine -> adjusted (fp32 output) + delta (bf16)
    combine_kernel<<<BATCH*SQ, 256>>>(kwpos, adj);
    // 7) out = sv/2048 + delta @ value   (exact decomposition)
    gemm_mma<4><<<dim3(4, 16, BATCH), 256>>>(
        gdelta, gvalT, nullptr, nullptr, out,
        SK, (long)SQ*SK, (long)512*SK, (long)SQ*512, SQ, gsv, nullptr);
}